// round 4
// baseline (speedup 1.0000x reference)
#include <cuda_runtime.h>
#include <math.h>

// Problem constants
#define NB 2
#define NQ 75
#define NN 5
#define NT 196
#define NC 384
#define ND 384
#define NCHUNK 6          // 384 / 64 c1-chunks
#define C1 64
#define SCALE_ATT (1.0f/14.0f)   // 1/sqrt(k*t) = 1/sqrt(196)

#define BQN (NB*NQ*NN)    // 750
#define NBQ (NB*NQ)       // 150

// Deterministic global scratch (per-chunk partials; every element written each run)
__device__ float g_num[(size_t)BQN*NCHUNK*NT];
__device__ float g_nq [(size_t)BQN*NCHUNK*NT];
__device__ float g_ns [NB*NN*NT];

// Packed fp32x2 FMA (sm_100+; ptxas never emits this from C++ — 2x FFMA throughput)
__device__ __forceinline__ float2 ffma2(float2 a, float2 b, float2 c){
    unsigned long long au = *reinterpret_cast<unsigned long long*>(&a);
    unsigned long long bu = *reinterpret_cast<unsigned long long*>(&b);
    unsigned long long cu = *reinterpret_cast<unsigned long long*>(&c);
    unsigned long long du;
    asm("fma.rn.f32x2 %0, %1, %2, %3;" : "=l"(du) : "l"(au), "l"(bu), "l"(cu));
    return *reinterpret_cast<float2*>(&du);
}

// ---------------------------------------------------------------------------
// ns[t] = sum_c FS[t,c]^2 per (b,n)
// ---------------------------------------------------------------------------
__global__ void ns_kernel(const float* __restrict__ fs_all){
    int bn = blockIdx.x;
    int t = threadIdx.x;
    if(t >= NT) return;
    const float* p = fs_all + ((size_t)bn*NT + t)*NC;
    float s = 0.f;
    #pragma unroll 4
    for(int c = 0; c < NC; c += 4){
        float4 v = *reinterpret_cast<const float4*>(p + c);
        s += v.x*v.x + v.y*v.y + v.z*v.z + v.w*v.w;
    }
    g_ns[bn*NT + t] = s;
}

// ---------------------------------------------------------------------------
// Main fused kernel: one CTA per (b,q,n, c1-chunk of 64)
//   GEMM1: A[64][384] = FQ[:,chunk]^T * FS / 14   (K = 196)
//   softmax rows of A
//   GEMM2: V[196][64] = FQ * A^T                  (K = 384)
//   partial num[t], nq[t] written to global scratch
// SMEM: sA 64x388 | staging union (FS 32x388 / FQ 224x68) | FQt 32x68
// ---------------------------------------------------------------------------
#define OFF_ST  24832
#define OFF_FQT 40064
#define SMEM_BYTES (42240*4)   // 168960 B

__global__ __launch_bounds__(512,1)
void main_kernel(const float* __restrict__ fq_all, const float* __restrict__ fs_all){
    extern __shared__ float sm[];
    float* sA   = sm;            // [64][388]
    float* sSt  = sm + OFF_ST;   // staging
    float* sFQt = sm + OFF_FQT;  // [32][68]

    int blk   = blockIdx.x;
    int chunk = blk % NCHUNK;
    int bqn   = blk / NCHUNK;
    int n     = bqn % NN;
    int bq    = bqn / NN;
    int b     = bq / NQ;
    const float* FQ = fq_all + (size_t)bq*NT*NC;
    const float* FS = fs_all + (size_t)(b*NN + n)*NT*NC;
    int c1base = chunk*C1;

    int tid = threadIdx.x;
    int tx  = tid & 31;    // GEMM1: c2 pair dim (warp lanes)
    int ty  = tid >> 5;    // GEMM1: c1 row group [0,16)

    // ---------------- GEMM1: A = FQ_chunk^T * FS ----------------
    float2 acc[4][6];
    #pragma unroll
    for(int r = 0; r < 4; ++r)
        #pragma unroll
        for(int p = 0; p < 6; ++p) acc[r][p] = make_float2(0.f, 0.f);

    for(int kt = 0; kt < 7; ++kt){
        int t0 = kt*32;
        // stage FQt[32][64] (a-matrix slice, zero-padded past t=196)
        {
            int k  = tid >> 4;
            int i4 = tid & 15;
            int t  = t0 + k;
            float4 v = make_float4(0.f,0.f,0.f,0.f);
            if(t < NT) v = *reinterpret_cast<const float4*>(FQ + (size_t)t*NC + c1base + i4*4);
            *reinterpret_cast<float4*>(sFQt + k*68 + i4*4) = v;
        }
        // stage FSt[32][384] (b-matrix slice)
        #pragma unroll
        for(int p = 0; p < 6; ++p){
            int j  = tid + p*512;
            int k  = j / 96;
            int c4 = j - k*96;
            int t  = t0 + k;
            float4 v = make_float4(0.f,0.f,0.f,0.f);
            if(t < NT) v = *reinterpret_cast<const float4*>(FS + (size_t)t*NC + c4*4);
            *reinterpret_cast<float4*>(sSt + k*388 + c4*4) = v;
        }
        __syncthreads();
        #pragma unroll 8
        for(int kk = 0; kk < 32; ++kk){
            float4 a4 = *reinterpret_cast<const float4*>(sFQt + kk*68 + ty*4);
            float2 a0 = make_float2(a4.x, a4.x);
            float2 a1 = make_float2(a4.y, a4.y);
            float2 a2 = make_float2(a4.z, a4.z);
            float2 a3 = make_float2(a4.w, a4.w);
            #pragma unroll
            for(int p = 0; p < 6; ++p){
                float2 bb = *reinterpret_cast<const float2*>(sSt + kk*388 + 2*(tx + 32*p));
                acc[0][p] = ffma2(a0, bb, acc[0][p]);
                acc[1][p] = ffma2(a1, bb, acc[1][p]);
                acc[2][p] = ffma2(a2, bb, acc[2][p]);
                acc[3][p] = ffma2(a3, bb, acc[3][p]);
            }
        }
        __syncthreads();
    }

    // write A (scaled)
    #pragma unroll
    for(int r = 0; r < 4; ++r){
        float* row = sA + (ty*4 + r)*388;
        #pragma unroll
        for(int p = 0; p < 6; ++p){
            float2 v = acc[r][p];
            v.x *= SCALE_ATT; v.y *= SCALE_ATT;
            *reinterpret_cast<float2*>(row + 2*(tx + 32*p)) = v;
        }
    }
    __syncthreads();

    // ---------------- softmax per row (warp w -> rows 4w..4w+3) ----------------
    {
        #pragma unroll
        for(int r = 0; r < 4; ++r){
            float* row = sA + (ty*4 + r)*388;
            float v[12];
            float m = -1e30f;
            #pragma unroll
            for(int i = 0; i < 12; ++i){ v[i] = row[tx + 32*i]; m = fmaxf(m, v[i]); }
            #pragma unroll
            for(int o = 16; o; o >>= 1) m = fmaxf(m, __shfl_xor_sync(0xffffffffu, m, o));
            float s = 0.f;
            #pragma unroll
            for(int i = 0; i < 12; ++i){ v[i] = __expf(v[i] - m); s += v[i]; }
            #pragma unroll
            for(int o = 16; o; o >>= 1) s += __shfl_xor_sync(0xffffffffu, s, o);
            float inv = 1.0f / s;
            #pragma unroll
            for(int i = 0; i < 12; ++i) row[tx + 32*i] = v[i]*inv;
        }
    }
    __syncthreads();

    // ---------------- GEMM2: V[t][j] = sum_c2 FQ[t][c2] * P[j][c2] ----------------
    int jx  = tid & 15;   // j dim [0,16)
    int tyy = tid >> 4;   // t dim [0,32)
    float2 vacc[7][4];
    #pragma unroll
    for(int r = 0; r < 7; ++r)
        #pragma unroll
        for(int j = 0; j < 4; ++j) vacc[r][j] = make_float2(0.f, 0.f);

    for(int ct = 0; ct < 6; ++ct){
        int c2b = ct*64;
        // stage FQ[:,c2 tile] as [224][68] (zero-padded rows past 196)
        #pragma unroll
        for(int pass = 0; pass < 7; ++pass){
            int t = tyy + pass*32;
            float4 v = make_float4(0.f,0.f,0.f,0.f);
            if(t < NT) v = *reinterpret_cast<const float4*>(FQ + (size_t)t*NC + c2b + jx*4);
            *reinterpret_cast<float4*>(sSt + t*68 + jx*4) = v;
        }
        __syncthreads();
        #pragma unroll 4
        for(int cc = 0; cc < 16; ++cc){
            float2 plo[4], phi[4];
            #pragma unroll
            for(int jj = 0; jj < 4; ++jj){
                float4 p4 = *reinterpret_cast<const float4*>(sA + (jx + 16*jj)*388 + c2b + cc*4);
                plo[jj] = make_float2(p4.x, p4.y);
                phi[jj] = make_float2(p4.z, p4.w);
            }
            #pragma unroll
            for(int r = 0; r < 7; ++r){
                float4 f4 = *reinterpret_cast<const float4*>(sSt + (tyy + 32*r)*68 + cc*4);
                float2 flo = make_float2(f4.x, f4.y);
                float2 fhi = make_float2(f4.z, f4.w);
                #pragma unroll
                for(int jj = 0; jj < 4; ++jj){
                    vacc[r][jj] = ffma2(flo, plo[jj], vacc[r][jj]);
                    vacc[r][jj] = ffma2(fhi, phi[jj], vacc[r][jj]);
                }
            }
        }
        __syncthreads();
    }

    // ---------------- per-t partial num / nq, reduce over 16 j-lanes ----------------
    #pragma unroll
    for(int r = 0; r < 7; ++r){
        int t = tyy + 32*r;
        bool valid = (t < NT);
        float pn = 0.f, pq = 0.f;
        #pragma unroll
        for(int jj = 0; jj < 4; ++jj){
            float v   = vacc[r][jj].x + vacc[r][jj].y;
            float fsv = valid ? FS[(size_t)t*NC + c1base + jx + 16*jj] : 0.f;
            pn += v*fsv;
            pq += v*v;
        }
        #pragma unroll
        for(int o = 8; o; o >>= 1){
            pn += __shfl_down_sync(0xffffffffu, pn, o, 16);
            pq += __shfl_down_sync(0xffffffffu, pq, o, 16);
        }
        if(jx == 0 && valid){
            size_t idx = ((size_t)bqn*NCHUNK + chunk)*NT + t;
            g_num[idx] = pn;
            g_nq [idx] = pq;
        }
    }
}

// ---------------------------------------------------------------------------
// Finalize: sim -> max over t -> mean over n -> logits ; plus cls_logits branch
// ---------------------------------------------------------------------------
__global__ void finalize_kernel(const float* __restrict__ xq_all,
                                const float* __restrict__ xs_all,
                                float* __restrict__ out, int loOff, int clsOff){
    int bq  = blockIdx.x;          // 0..149
    int b   = bq / NQ;
    int tid = threadIdx.x;         // 256
    int lane = tid & 31, w = tid >> 5;
    __shared__ float red[8];
    __shared__ float accs;
    if(tid == 0) accs = 0.f;
    __syncthreads();

    for(int n = 0; n < NN; ++n){
        int bqn = bq*NN + n;
        const float* nsrow = g_ns + (b*NN + n)*NT;
        float m = -1e30f;
        for(int t = tid; t < NT; t += 256){
            float sn = 0.f, sq = 0.f;
            #pragma unroll
            for(int ch = 0; ch < NCHUNK; ++ch){
                size_t idx = ((size_t)bqn*NCHUNK + ch)*NT + t;
                sn += g_num[idx];
                sq += g_nq [idx];
            }
            float denom = fmaxf(sqrtf(sq)*sqrtf(nsrow[t]), 1e-8f);
            m = fmaxf(m, sn/denom);
        }
        #pragma unroll
        for(int o = 16; o; o >>= 1) m = fmaxf(m, __shfl_xor_sync(0xffffffffu, m, o));
        if(lane == 0) red[w] = m;
        __syncthreads();
        if(tid == 0){
            float r = red[0];
            #pragma unroll
            for(int i = 1; i < 8; ++i) r = fmaxf(r, red[i]);
            accs += r;
        }
        __syncthreads();
    }
    if(tid == 0 && loOff >= 0) out[loOff + bq] = accs * (1.0f/NN);

    // prototype classification branch: warp n handles class n
    if(clsOff >= 0 && w < NN){
        int n = w;
        const float* xq = xq_all + (size_t)bq*ND;
        const float* xs = xs_all + (size_t)(b*NN + n)*ND;
        float dq = 0.f, ds = 0.f, dd = 0.f;
        for(int c = lane; c < ND; c += 32){
            float a = xq[c], s = xs[c];
            dq += a*a; ds += s*s; dd += a*s;
        }
        #pragma unroll
        for(int o = 16; o; o >>= 1){
            dq += __shfl_xor_sync(0xffffffffu, dq, o);
            ds += __shfl_xor_sync(0xffffffffu, ds, o);
            dd += __shfl_xor_sync(0xffffffffu, dd, o);
        }
        if(lane == 0){
            float na = fmaxf(sqrtf(dq), 1e-12f);
            float nb = fmaxf(sqrtf(ds), 1e-12f);
            out[clsOff + bq*NN + n] = 10.0f * dd / (na*nb);
        }
    }
}

// ---------------------------------------------------------------------------
extern "C" void kernel_launch(void* const* d_in, const int* in_sizes, int n_in,
                              void* d_out, int out_size){
    const float* fq = (const float*)d_in[0];  // (2,75,196,384)
    const float* fs = (const float*)d_in[1];  // (2,5,1,196,384)
    const float* xq = (const float*)d_in[2];  // (2,75,384)
    const float* xs = (const float*)d_in[3];  // (2,5,1,384)

    cudaFuncSetAttribute(main_kernel, cudaFuncAttributeMaxDynamicSharedMemorySize, SMEM_BYTES);

    ns_kernel<<<NB*NN, 224>>>(fs);
    main_kernel<<<BQN*NCHUNK, 512, SMEM_BYTES>>>(fq, fs);

    int loOff = -1, clsOff = -1;
    if(out_size >= NBQ + BQN){ loOff = 0; clsOff = NBQ; }      // 900: both, logits first
    else if(out_size == NBQ){ loOff = 0; }                     // 150: logits only
    else if(out_size == BQN){ clsOff = 0; }                    // 750: cls only
    else { loOff = 0; }                                        // fallback
    finalize_kernel<<<NBQ, 256>>>(xq, xs, (float*)d_out, loOff, clsOff);
}

// round 6
// speedup vs baseline: 1.0191x; 1.0191x over previous
#include <cuda_runtime.h>
#include <math.h>

// Problem constants
#define NB 2
#define NQ 75
#define NN 5
#define NT 196
#define NC 384
#define ND 384
#define NCHUNK 6          // 384 / 64 c1-chunks
#define C1 64
#define SCALE_ATT (1.0f/14.0f)   // 1/sqrt(k*t) = 1/sqrt(196)

#define BQN (NB*NQ*NN)    // 750
#define NBQ (NB*NQ)       // 150

// Deterministic global scratch (per-chunk partials; every element written each run)
__device__ float g_num[(size_t)BQN*NCHUNK*NT];
__device__ float g_nq [(size_t)BQN*NCHUNK*NT];
__device__ float g_ns [NB*NN*NT];

// Packed fp32x2 FMA (sm_100+; ptxas never emits this from C++ — 2x FFMA throughput)
__device__ __forceinline__ float2 ffma2(float2 a, float2 b, float2 c){
    unsigned long long au = *reinterpret_cast<unsigned long long*>(&a);
    unsigned long long bu = *reinterpret_cast<unsigned long long*>(&b);
    unsigned long long cu = *reinterpret_cast<unsigned long long*>(&c);
    unsigned long long du;
    asm("fma.rn.f32x2 %0, %1, %2, %3;" : "=l"(du) : "l"(au), "l"(bu), "l"(cu));
    return *reinterpret_cast<float2*>(&du);
}

// ---------------------------------------------------------------------------
// ns[t] = sum_c FS[t,c]^2 per (b,n)
// ---------------------------------------------------------------------------
__global__ void ns_kernel(const float* __restrict__ fs_all){
    int bn = blockIdx.x;
    int t = threadIdx.x;
    if(t >= NT) return;
    const float* p = fs_all + ((size_t)bn*NT + t)*NC;
    float s = 0.f;
    #pragma unroll 4
    for(int c = 0; c < NC; c += 4){
        float4 v = *reinterpret_cast<const float4*>(p + c);
        s += v.x*v.x + v.y*v.y + v.z*v.z + v.w*v.w;
    }
    g_ns[bn*NT + t] = s;
}

// ---------------------------------------------------------------------------
// Main fused kernel: one CTA per (b,q,n, c1-chunk of 64)
//   GEMM1: A[64][384] = FQ[:,chunk]^T * FS / 14   (K = 196)  [8x6 thread tile]
//   softmax rows of A
//   GEMM2: V[196][64] = FQ * A^T                  (K = 384)
//   partial num[t], nq[t] written to global scratch
// SMEM: sA 64x388 | staging union (FS 32x388 / FQ 224x68) | FQt 32x68
// ---------------------------------------------------------------------------
#define OFF_ST  24832
#define OFF_FQT 40064
#define SMEM_BYTES (42240*4)   // 168960 B

__global__ __launch_bounds__(512,1)
void main_kernel(const float* __restrict__ fq_all, const float* __restrict__ fs_all){
    extern __shared__ float sm[];
    float* sA   = sm;            // [64][388]
    float* sSt  = sm + OFF_ST;   // staging (15232 floats)
    float* sFQt = sm + OFF_FQT;  // [32][68]

    int blk   = blockIdx.x;
    int chunk = blk % NCHUNK;
    int bqn   = blk / NCHUNK;
    int n     = bqn % NN;
    int bq    = bqn / NN;
    int b     = bq / NQ;
    const float* FQ = fq_all + (size_t)bq*NT*NC;
    const float* FS = fs_all + (size_t)(b*NN + n)*NT*NC;
    int c1base = chunk*C1;

    int tid  = threadIdx.x;
    int lane = tid & 31;
    int warp = tid >> 5;

    // ---------------- GEMM1: A = FQ_chunk^T * FS (8 rows x 6 c2 per thread) ----
    int rowg = warp >> 1;              // 0..7  -> rows rowg*8 .. +7
    int colg = warp & 1;               // 0..1  -> c2 half
    int c2o  = colg*192 + 2*lane;      // + 64*p, p=0..2

    float2 acc[8][3];
    #pragma unroll
    for(int r = 0; r < 8; ++r)
        #pragma unroll
        for(int p = 0; p < 3; ++p) acc[r][p] = make_float2(0.f, 0.f);

    // staging index precompute
    int sk  = tid >> 4;                // FQt row 0..31
    int si4 = tid & 15;                // FQt col group

    float4 pfq;            // FQt prefetch
    float4 pfs[6];         // FS prefetch

    // prefetch kt=0
    {
        int t = sk;
        pfq = make_float4(0.f,0.f,0.f,0.f);
        if(t < NT) pfq = *reinterpret_cast<const float4*>(FQ + (size_t)t*NC + c1base + si4*4);
        #pragma unroll
        for(int p = 0; p < 6; ++p){
            int j = tid + p*512, k = j/96, c4 = j - k*96;
            pfs[p] = make_float4(0.f,0.f,0.f,0.f);
            if(k < NT) pfs[p] = *reinterpret_cast<const float4*>(FS + (size_t)k*NC + c4*4);
        }
    }

    #define G1_STORE() do{ \
        *reinterpret_cast<float4*>(sFQt + sk*68 + si4*4) = pfq; \
        _Pragma("unroll") \
        for(int p = 0; p < 6; ++p){ \
            int j = tid + p*512, k = j/96, c4 = j - k*96; \
            *reinterpret_cast<float4*>(sSt + k*388 + c4*4) = pfs[p]; \
        } }while(0)

    #define G1_KK(kk) do{ \
        float4 fa = *reinterpret_cast<const float4*>(sFQt + (kk)*68 + rowg*8); \
        float4 fb = *reinterpret_cast<const float4*>(sFQt + (kk)*68 + rowg*8 + 4); \
        float av[8] = {fa.x,fa.y,fa.z,fa.w,fb.x,fb.y,fb.z,fb.w}; \
        float2 b0 = *reinterpret_cast<const float2*>(sSt + (kk)*388 + c2o); \
        float2 b1 = *reinterpret_cast<const float2*>(sSt + (kk)*388 + c2o + 64); \
        float2 b2 = *reinterpret_cast<const float2*>(sSt + (kk)*388 + c2o + 128); \
        _Pragma("unroll") \
        for(int r = 0; r < 8; ++r){ \
            float2 ad = make_float2(av[r], av[r]); \
            acc[r][0] = ffma2(ad, b0, acc[r][0]); \
            acc[r][1] = ffma2(ad, b1, acc[r][1]); \
            acc[r][2] = ffma2(ad, b2, acc[r][2]); \
        } }while(0)

    for(int kt = 0; kt < 6; ++kt){
        __syncthreads();
        G1_STORE();
        __syncthreads();
        // prefetch next slice (hidden behind compute below)
        {
            int t0n = (kt+1)*32;
            int t = t0n + sk;
            pfq = make_float4(0.f,0.f,0.f,0.f);
            if(t < NT) pfq = *reinterpret_cast<const float4*>(FQ + (size_t)t*NC + c1base + si4*4);
            #pragma unroll
            for(int p = 0; p < 6; ++p){
                int j = tid + p*512, k = j/96, c4 = j - k*96;
                int tt = t0n + k;
                pfs[p] = make_float4(0.f,0.f,0.f,0.f);
                if(tt < NT) pfs[p] = *reinterpret_cast<const float4*>(FS + (size_t)tt*NC + c4*4);
            }
        }
        #pragma unroll 8
        for(int kk = 0; kk < 32; ++kk) G1_KK(kk);
    }
    // tail: kt = 6, only t = 192..195 valid -> 4 kk
    __syncthreads();
    G1_STORE();
    __syncthreads();
    #pragma unroll
    for(int kk = 0; kk < 4; ++kk) G1_KK(kk);

    // write A (scaled) — rows rowg*8..+7, cols c2o + 64p
    #pragma unroll
    for(int r = 0; r < 8; ++r){
        float* row = sA + (rowg*8 + r)*388;
        #pragma unroll
        for(int p = 0; p < 3; ++p){
            float2 v = acc[r][p];
            v.x *= SCALE_ATT; v.y *= SCALE_ATT;
            *reinterpret_cast<float2*>(row + c2o + 64*p) = v;
        }
    }
    __syncthreads();

    // ---------------- softmax per row (warp w -> rows 4w..4w+3) ----------------
    {
        int tx = lane, ty = warp;
        #pragma unroll
        for(int r = 0; r < 4; ++r){
            float* row = sA + (ty*4 + r)*388;
            float v[12];
            float m = -1e30f;
            #pragma unroll
            for(int i = 0; i < 12; ++i){ v[i] = row[tx + 32*i]; m = fmaxf(m, v[i]); }
            #pragma unroll
            for(int o = 16; o; o >>= 1) m = fmaxf(m, __shfl_xor_sync(0xffffffffu, m, o));
            float s = 0.f;
            #pragma unroll
            for(int i = 0; i < 12; ++i){ v[i] = __expf(v[i] - m); s += v[i]; }
            #pragma unroll
            for(int o = 16; o; o >>= 1) s += __shfl_xor_sync(0xffffffffu, s, o);
            float inv = 1.0f / s;
            #pragma unroll
            for(int i = 0; i < 12; ++i) row[tx + 32*i] = v[i]*inv;
        }
    }
    __syncthreads();

    // ---------------- GEMM2: V[t][j] = sum_c2 FQ[t][c2] * P[j][c2] ----------------
    int jx  = tid & 15;   // j dim [0,16)
    int tyy = tid >> 4;   // t dim [0,32)
    float2 vacc[7][4];
    #pragma unroll
    for(int r = 0; r < 7; ++r)
        #pragma unroll
        for(int j = 0; j < 4; ++j) vacc[r][j] = make_float2(0.f, 0.f);

    for(int ct = 0; ct < 6; ++ct){
        int c2b = ct*64;
        // issue loads before barrier (overlap LDG with barrier wait)
        float4 pq[7];
        #pragma unroll
        for(int pass = 0; pass < 7; ++pass){
            int t = tyy + pass*32;
            pq[pass] = make_float4(0.f,0.f,0.f,0.f);
            if(t < NT) pq[pass] = *reinterpret_cast<const float4*>(FQ + (size_t)t*NC + c2b + jx*4);
        }
        __syncthreads();
        #pragma unroll
        for(int pass = 0; pass < 7; ++pass)
            *reinterpret_cast<float4*>(sSt + (tyy + pass*32)*68 + jx*4) = pq[pass];
        __syncthreads();
        #pragma unroll 4
        for(int cc = 0; cc < 16; ++cc){
            float2 plo[4], phi[4];
            #pragma unroll
            for(int jj = 0; jj < 4; ++jj){
                float4 p4 = *reinterpret_cast<const float4*>(sA + (jx + 16*jj)*388 + c2b + cc*4);
                plo[jj] = make_float2(p4.x, p4.y);
                phi[jj] = make_float2(p4.z, p4.w);
            }
            #pragma unroll
            for(int r = 0; r < 7; ++r){
                float4 f4 = *reinterpret_cast<const float4*>(sSt + (tyy + 32*r)*68 + cc*4);
                float2 flo = make_float2(f4.x, f4.y);
                float2 fhi = make_float2(f4.z, f4.w);
                #pragma unroll
                for(int jj = 0; jj < 4; ++jj){
                    vacc[r][jj] = ffma2(flo, plo[jj], vacc[r][jj]);
                    vacc[r][jj] = ffma2(fhi, phi[jj], vacc[r][jj]);
                }
            }
        }
    }

    // ---------------- per-t partial num / nq, reduce over 16 j-lanes ----------------
    #pragma unroll
    for(int r = 0; r < 7; ++r){
        int t = tyy + 32*r;
        bool valid = (t < NT);
        float pn = 0.f, pq2 = 0.f;
        #pragma unroll
        for(int jj = 0; jj < 4; ++jj){
            float v   = vacc[r][jj].x + vacc[r][jj].y;
            float fsv = valid ? FS[(size_t)t*NC + c1base + jx + 16*jj] : 0.f;
            pn  += v*fsv;
            pq2 += v*v;
        }
        #pragma unroll
        for(int o = 8; o; o >>= 1){
            pn  += __shfl_down_sync(0xffffffffu, pn, o, 16);
            pq2 += __shfl_down_sync(0xffffffffu, pq2, o, 16);
        }
        if(jx == 0 && valid){
            size_t idx = ((size_t)bqn*NCHUNK + chunk)*NT + t;
            g_num[idx] = pn;
            g_nq [idx] = pq2;
        }
    }
}

// ---------------------------------------------------------------------------
// Finalize: sim -> max over t -> mean over n -> logits ; plus cls_logits branch
// ---------------------------------------------------------------------------
__global__ void finalize_kernel(const float* __restrict__ xq_all,
                                const float* __restrict__ xs_all,
                                float* __restrict__ out, int loOff, int clsOff){
    int bq  = blockIdx.x;          // 0..149
    int b   = bq / NQ;
    int tid = threadIdx.x;         // 256
    int lane = tid & 31, w = tid >> 5;
    __shared__ float red[8];
    __shared__ float accs;
    if(tid == 0) accs = 0.f;
    __syncthreads();

    for(int n = 0; n < NN; ++n){
        int bqn = bq*NN + n;
        const float* nsrow = g_ns + (b*NN + n)*NT;
        float m = -1e30f;
        for(int t = tid; t < NT; t += 256){
            float sn = 0.f, sq = 0.f;
            #pragma unroll
            for(int ch = 0; ch < NCHUNK; ++ch){
                size_t idx = ((size_t)bqn*NCHUNK + ch)*NT + t;
                sn += g_num[idx];
                sq += g_nq [idx];
            }
            float denom = fmaxf(sqrtf(sq)*sqrtf(nsrow[t]), 1e-8f);
            m = fmaxf(m, sn/denom);
        }
        #pragma unroll
        for(int o = 16; o; o >>= 1) m = fmaxf(m, __shfl_xor_sync(0xffffffffu, m, o));
        if(lane == 0) red[w] = m;
        __syncthreads();
        if(tid == 0){
            float r = red[0];
            #pragma unroll
            for(int i = 1; i < 8; ++i) r = fmaxf(r, red[i]);
            accs += r;
        }
        __syncthreads();
    }
    if(tid == 0 && loOff >= 0) out[loOff + bq] = accs * (1.0f/NN);

    // prototype classification branch: warp n handles class n
    if(clsOff >= 0 && w < NN){
        int n = w;
        const float* xq = xq_all + (size_t)bq*ND;
        const float* xs = xs_all + (size_t)(b*NN + n)*ND;
        float dq = 0.f, ds = 0.f, dd = 0.f;
        for(int c = lane; c < ND; c += 32){
            float a = xq[c], s = xs[c];
            dq += a*a; ds += s*s; dd += a*s;
        }
        #pragma unroll
        for(int o = 16; o; o >>= 1){
            dq += __shfl_xor_sync(0xffffffffu, dq, o);
            ds += __shfl_xor_sync(0xffffffffu, ds, o);
            dd += __shfl_xor_sync(0xffffffffu, dd, o);
        }
        if(lane == 0){
            float na = fmaxf(sqrtf(dq), 1e-12f);
            float nb = fmaxf(sqrtf(ds), 1e-12f);
            out[clsOff + bq*NN + n] = 10.0f * dd / (na*nb);
        }
    }
}

// ---------------------------------------------------------------------------
extern "C" void kernel_launch(void* const* d_in, const int* in_sizes, int n_in,
                              void* d_out, int out_size){
    const float* fq = (const float*)d_in[0];  // (2,75,196,384)
    const float* fs = (const float*)d_in[1];  // (2,5,1,196,384)
    const float* xq = (const float*)d_in[2];  // (2,75,384)
    const float* xs = (const float*)d_in[3];  // (2,5,1,384)

    cudaFuncSetAttribute(main_kernel, cudaFuncAttributeMaxDynamicSharedMemorySize, SMEM_BYTES);

    ns_kernel<<<NB*NN, 224>>>(fs);
    main_kernel<<<BQN*NCHUNK, 512, SMEM_BYTES>>>(fq, fs);

    int loOff = -1, clsOff = -1;
    if(out_size >= NBQ + BQN){ loOff = 0; clsOff = NBQ; }      // 900: both, logits first
    else if(out_size == NBQ){ loOff = 0; }                     // 150: logits only
    else if(out_size == BQN){ clsOff = 0; }                    // 750: cls only
    else { loOff = 0; }                                        // fallback
    finalize_kernel<<<NBQ, 256>>>(xq, xs, (float*)d_out, loOff, clsOff);
}

// round 9
// speedup vs baseline: 1.1035x; 1.0828x over previous
#include <cuda_runtime.h>
#include <math.h>

// Problem constants
#define NB 2
#define NQ 75
#define NN 5
#define NT 196
#define NC 384
#define ND 384
#define NCHUNK 6          // 384 / 64 c1-chunks
#define C1 64
#define SCALE_ATT (1.0f/14.0f)   // 1/sqrt(k*t) = 1/sqrt(196)

#define BQN (NB*NQ*NN)    // 750
#define NBQ (NB*NQ)       // 150

// Deterministic global scratch (per-chunk partials; every element written each run)
__device__ float g_num[(size_t)BQN*NCHUNK*NT];
__device__ float g_nq [(size_t)BQN*NCHUNK*NT];
__device__ float g_ns [NB*NN*NT];

// Packed fp32x2 FMA (sm_100+; ptxas never emits this from C++ — 2x FFMA throughput)
__device__ __forceinline__ float2 ffma2(float2 a, float2 b, float2 c){
    unsigned long long au = *reinterpret_cast<unsigned long long*>(&a);
    unsigned long long bu = *reinterpret_cast<unsigned long long*>(&b);
    unsigned long long cu = *reinterpret_cast<unsigned long long*>(&c);
    unsigned long long du;
    asm("fma.rn.f32x2 %0, %1, %2, %3;" : "=l"(du) : "l"(au), "l"(bu), "l"(cu));
    return *reinterpret_cast<float2*>(&du);
}

// ---------------------------------------------------------------------------
// ns[t] = sum_c FS[t,c]^2 per (b,n)
// ---------------------------------------------------------------------------
__global__ void ns_kernel(const float* __restrict__ fs_all){
    int bn = blockIdx.x;
    int t = threadIdx.x;
    if(t >= NT) return;
    const float* p = fs_all + ((size_t)bn*NT + t)*NC;
    float s = 0.f;
    #pragma unroll 4
    for(int c = 0; c < NC; c += 4){
        float4 v = *reinterpret_cast<const float4*>(p + c);
        s += v.x*v.x + v.y*v.y + v.z*v.z + v.w*v.w;
    }
    g_ns[bn*NT + t] = s;
}

// ---------------------------------------------------------------------------
// Main fused kernel: one CTA per (b,q,n, c1-chunk of 64)
//   GEMM1: A[64][384] = FQ[:,chunk]^T * FS / 14   (K = 196)  [8x6 thread tile]
//   softmax rows of A
//   GEMM2: V[196][64] = FQ * A^T                  (K = 384)   [t-tail trimmed]
//   partial num[t], nq[t] written to global scratch
// SMEM: sA 64x388 | staging union (FS 32x388 / FQ 224x68) | FQt 32x68
// ---------------------------------------------------------------------------
#define OFF_ST  24832
#define OFF_FQT 40064
#define SMEM_BYTES (42240*4)   // 168960 B

__global__ __launch_bounds__(512,1)
void main_kernel(const float* __restrict__ fq_all, const float* __restrict__ fs_all){
    extern __shared__ float sm[];
    float* sA   = sm;            // [64][388]
    float* sSt  = sm + OFF_ST;   // staging (15232 floats)
    float* sFQt = sm + OFF_FQT;  // [32][68]

    int blk   = blockIdx.x;
    int chunk = blk % NCHUNK;
    int bqn   = blk / NCHUNK;
    int n     = bqn % NN;
    int bq    = bqn / NN;
    int b     = bq / NQ;
    const float* FQ = fq_all + (size_t)bq*NT*NC;
    const float* FS = fs_all + (size_t)(b*NN + n)*NT*NC;
    int c1base = chunk*C1;

    int tid  = threadIdx.x;
    int lane = tid & 31;
    int warp = tid >> 5;

    // ---------------- GEMM1: A = FQ_chunk^T * FS (8 rows x 6 c2 per thread) ----
    int rowg = warp >> 1;              // 0..7  -> rows rowg*8 .. +7
    int colg = warp & 1;               // 0..1  -> c2 half
    int c2o  = colg*192 + 2*lane;      // + 64*p, p=0..2

    float2 acc[8][3];
    #pragma unroll
    for(int r = 0; r < 8; ++r)
        #pragma unroll
        for(int p = 0; p < 3; ++p) acc[r][p] = make_float2(0.f, 0.f);

    // staging index precompute
    int sk  = tid >> 4;                // FQt row 0..31
    int si4 = tid & 15;                // FQt col group

    float4 pfq;            // FQt prefetch
    float4 pfs[6];         // FS prefetch

    // prefetch kt=0
    {
        int t = sk;
        pfq = make_float4(0.f,0.f,0.f,0.f);
        if(t < NT) pfq = *reinterpret_cast<const float4*>(FQ + (size_t)t*NC + c1base + si4*4);
        #pragma unroll
        for(int p = 0; p < 6; ++p){
            int j = tid + p*512, k = j/96, c4 = j - k*96;
            pfs[p] = make_float4(0.f,0.f,0.f,0.f);
            if(k < NT) pfs[p] = *reinterpret_cast<const float4*>(FS + (size_t)k*NC + c4*4);
        }
    }

    #define G1_STORE() do{ \
        *reinterpret_cast<float4*>(sFQt + sk*68 + si4*4) = pfq; \
        _Pragma("unroll") \
        for(int p = 0; p < 6; ++p){ \
            int j = tid + p*512, k = j/96, c4 = j - k*96; \
            *reinterpret_cast<float4*>(sSt + k*388 + c4*4) = pfs[p]; \
        } }while(0)

    #define G1_KK(kk) do{ \
        float4 fa = *reinterpret_cast<const float4*>(sFQt + (kk)*68 + rowg*8); \
        float4 fb = *reinterpret_cast<const float4*>(sFQt + (kk)*68 + rowg*8 + 4); \
        float av[8] = {fa.x,fa.y,fa.z,fa.w,fb.x,fb.y,fb.z,fb.w}; \
        float2 b0 = *reinterpret_cast<const float2*>(sSt + (kk)*388 + c2o); \
        float2 b1 = *reinterpret_cast<const float2*>(sSt + (kk)*388 + c2o + 64); \
        float2 b2 = *reinterpret_cast<const float2*>(sSt + (kk)*388 + c2o + 128); \
        _Pragma("unroll") \
        for(int r = 0; r < 8; ++r){ \
            float2 ad = make_float2(av[r], av[r]); \
            acc[r][0] = ffma2(ad, b0, acc[r][0]); \
            acc[r][1] = ffma2(ad, b1, acc[r][1]); \
            acc[r][2] = ffma2(ad, b2, acc[r][2]); \
        } }while(0)

    for(int kt = 0; kt < 6; ++kt){
        __syncthreads();
        G1_STORE();
        __syncthreads();
        // prefetch next slice (hidden behind compute below)
        {
            int t0n = (kt+1)*32;
            int t = t0n + sk;
            pfq = make_float4(0.f,0.f,0.f,0.f);
            if(t < NT) pfq = *reinterpret_cast<const float4*>(FQ + (size_t)t*NC + c1base + si4*4);
            #pragma unroll
            for(int p = 0; p < 6; ++p){
                int j = tid + p*512, k = j/96, c4 = j - k*96;
                int tt = t0n + k;
                pfs[p] = make_float4(0.f,0.f,0.f,0.f);
                if(tt < NT) pfs[p] = *reinterpret_cast<const float4*>(FS + (size_t)tt*NC + c4*4);
            }
        }
        #pragma unroll 8
        for(int kk = 0; kk < 32; ++kk) G1_KK(kk);
    }
    // tail: kt = 6, only t = 192..195 valid -> 4 kk
    __syncthreads();
    G1_STORE();
    __syncthreads();
    #pragma unroll
    for(int kk = 0; kk < 4; ++kk) G1_KK(kk);

    // write A (scaled) — rows rowg*8..+7, cols c2o + 64p
    #pragma unroll
    for(int r = 0; r < 8; ++r){
        float* row = sA + (rowg*8 + r)*388;
        #pragma unroll
        for(int p = 0; p < 3; ++p){
            float2 v = acc[r][p];
            v.x *= SCALE_ATT; v.y *= SCALE_ATT;
            *reinterpret_cast<float2*>(row + c2o + 64*p) = v;
        }
    }
    __syncthreads();

    // ---------------- softmax per row (warp w -> rows 4w..4w+3) ----------------
    {
        int tx = lane, ty = warp;
        #pragma unroll
        for(int r = 0; r < 4; ++r){
            float* row = sA + (ty*4 + r)*388;
            float v[12];
            float m = -1e30f;
            #pragma unroll
            for(int i = 0; i < 12; ++i){ v[i] = row[tx + 32*i]; m = fmaxf(m, v[i]); }
            #pragma unroll
            for(int o = 16; o; o >>= 1) m = fmaxf(m, __shfl_xor_sync(0xffffffffu, m, o));
            float s = 0.f;
            #pragma unroll
            for(int i = 0; i < 12; ++i){ v[i] = __expf(v[i] - m); s += v[i]; }
            #pragma unroll
            for(int o = 16; o; o >>= 1) s += __shfl_xor_sync(0xffffffffu, s, o);
            float inv = 1.0f / s;
            #pragma unroll
            for(int i = 0; i < 12; ++i) row[tx + 32*i] = v[i]*inv;
        }
    }
    __syncthreads();

    // ---------------- GEMM2: V[t][j] = sum_c2 FQ[t][c2] * P[j][c2] ----------------
    // t-mapping: t = tyy + 32r ; r = 0..5 for all threads, r = 6 only for tyy < 4
    // (warp-uniform: warps 0,1 take the r=6 block, warps 2..15 skip it entirely)
    int jx  = tid & 15;   // j dim [0,16)
    int tyy = tid >> 4;   // t dim [0,32)
    bool tail = (tyy < 4);
    float2 vacc[7][4];
    #pragma unroll
    for(int r = 0; r < 7; ++r)
        #pragma unroll
        for(int j = 0; j < 4; ++j) vacc[r][j] = make_float2(0.f, 0.f);

    for(int ct = 0; ct < 6; ++ct){
        int c2b = ct*64;
        // issue loads before barrier (overlap LDG with barrier wait)
        float4 pq[7];
        #pragma unroll
        for(int pass = 0; pass < 7; ++pass){
            int t = tyy + pass*32;
            pq[pass] = make_float4(0.f,0.f,0.f,0.f);
            if(t < NT) pq[pass] = *reinterpret_cast<const float4*>(FQ + (size_t)t*NC + c2b + jx*4);
        }
        __syncthreads();
        #pragma unroll
        for(int pass = 0; pass < 7; ++pass){
            int t = tyy + pass*32;
            if(t < NT) *reinterpret_cast<float4*>(sSt + t*68 + jx*4) = pq[pass];
        }
        __syncthreads();
        #pragma unroll 4
        for(int cc = 0; cc < 16; ++cc){
            float2 plo[4], phi[4];
            #pragma unroll
            for(int jj = 0; jj < 4; ++jj){
                float4 p4 = *reinterpret_cast<const float4*>(sA + (jx + 16*jj)*388 + c2b + cc*4);
                plo[jj] = make_float2(p4.x, p4.y);
                phi[jj] = make_float2(p4.z, p4.w);
            }
            #pragma unroll
            for(int r = 0; r < 6; ++r){
                float4 f4 = *reinterpret_cast<const float4*>(sSt + (tyy + 32*r)*68 + cc*4);
                float2 flo = make_float2(f4.x, f4.y);
                float2 fhi = make_float2(f4.z, f4.w);
                #pragma unroll
                for(int jj = 0; jj < 4; ++jj){
                    vacc[r][jj] = ffma2(flo, plo[jj], vacc[r][jj]);
                    vacc[r][jj] = ffma2(fhi, phi[jj], vacc[r][jj]);
                }
            }
            if(tail){   // r = 6 : rows 192..195 only (warp-uniform branch)
                float4 f4 = *reinterpret_cast<const float4*>(sSt + (tyy + 192)*68 + cc*4);
                float2 flo = make_float2(f4.x, f4.y);
                float2 fhi = make_float2(f4.z, f4.w);
                #pragma unroll
                for(int jj = 0; jj < 4; ++jj){
                    vacc[6][jj] = ffma2(flo, plo[jj], vacc[6][jj]);
                    vacc[6][jj] = ffma2(fhi, phi[jj], vacc[6][jj]);
                }
            }
        }
    }

    // ---------------- per-t partial num / nq, reduce over 16 j-lanes ----------------
    #pragma unroll
    for(int r = 0; r < 7; ++r){
        int t = tyy + 32*r;
        bool valid = (t < NT);
        float pn = 0.f, pq2 = 0.f;
        #pragma unroll
        for(int jj = 0; jj < 4; ++jj){
            float v   = vacc[r][jj].x + vacc[r][jj].y;
            float fsv = valid ? FS[(size_t)t*NC + c1base + jx + 16*jj] : 0.f;
            pn  += v*fsv;
            pq2 += v*v;
        }
        #pragma unroll
        for(int o = 8; o; o >>= 1){
            pn  += __shfl_down_sync(0xffffffffu, pn, o, 16);
            pq2 += __shfl_down_sync(0xffffffffu, pq2, o, 16);
        }
        if(jx == 0 && valid){
            size_t idx = ((size_t)bqn*NCHUNK + chunk)*NT + t;
            g_num[idx] = pn;
            g_nq [idx] = pq2;
        }
    }
}

// ---------------------------------------------------------------------------
// Finalize: sim -> max over t -> mean over n -> logits ; plus cls_logits branch
// ---------------------------------------------------------------------------
__global__ void finalize_kernel(const float* __restrict__ xq_all,
                                const float* __restrict__ xs_all,
                                float* __restrict__ out, int loOff, int clsOff){
    int bq  = blockIdx.x;          // 0..149
    int b   = bq / NQ;
    int tid = threadIdx.x;         // 256
    int lane = tid & 31, w = tid >> 5;
    __shared__ float red[8];
    __shared__ float accs;
    if(tid == 0) accs = 0.f;
    __syncthreads();

    for(int n = 0; n < NN; ++n){
        int bqn = bq*NN + n;
        const float* nsrow = g_ns + (b*NN + n)*NT;
        float m = -1e30f;
        for(int t = tid; t < NT; t += 256){
            float sn = 0.f, sq = 0.f;
            #pragma unroll
            for(int ch = 0; ch < NCHUNK; ++ch){
                size_t idx = ((size_t)bqn*NCHUNK + ch)*NT + t;
                sn += g_num[idx];
                sq += g_nq [idx];
            }
            float denom = fmaxf(sqrtf(sq)*sqrtf(nsrow[t]), 1e-8f);
            m = fmaxf(m, sn/denom);
        }
        #pragma unroll
        for(int o = 16; o; o >>= 1) m = fmaxf(m, __shfl_xor_sync(0xffffffffu, m, o));
        if(lane == 0) red[w] = m;
        __syncthreads();
        if(tid == 0){
            float r = red[0];
            #pragma unroll
            for(int i = 1; i < 8; ++i) r = fmaxf(r, red[i]);
            accs += r;
        }
        __syncthreads();
    }
    if(tid == 0 && loOff >= 0) out[loOff + bq] = accs * (1.0f/NN);

    // prototype classification branch: warp n handles class n
    if(clsOff >= 0 && w < NN){
        int n = w;
        const float* xq = xq_all + (size_t)bq*ND;
        const float* xs = xs_all + (size_t)(b*NN + n)*ND;
        float dq = 0.f, ds = 0.f, dd = 0.f;
        for(int c = lane; c < ND; c += 32){
            float a = xq[c], s = xs[c];
            dq += a*a; ds += s*s; dd += a*s;
        }
        #pragma unroll
        for(int o = 16; o; o >>= 1){
            dq += __shfl_xor_sync(0xffffffffu, dq, o);
            ds += __shfl_xor_sync(0xffffffffu, ds, o);
            dd += __shfl_xor_sync(0xffffffffu, dd, o);
        }
        if(lane == 0){
            float na = fmaxf(sqrtf(dq), 1e-12f);
            float nb = fmaxf(sqrtf(ds), 1e-12f);
            out[clsOff + bq*NN + n] = 10.0f * dd / (na*nb);
        }
    }
}

// ---------------------------------------------------------------------------
extern "C" void kernel_launch(void* const* d_in, const int* in_sizes, int n_in,
                              void* d_out, int out_size){
    const float* fq = (const float*)d_in[0];  // (2,75,196,384)
    const float* fs = (const float*)d_in[1];  // (2,5,1,196,384)
    const float* xq = (const float*)d_in[2];  // (2,75,384)
    const float* xs = (const float*)d_in[3];  // (2,5,1,384)

    cudaFuncSetAttribute(main_kernel, cudaFuncAttributeMaxDynamicSharedMemorySize, SMEM_BYTES);

    // main first (independent of ns) so the fixed ncu capture window
    // (-s 5 -c 1), which has been landing on the first kernel of a replay,
    // profiles main_kernel instead of ns_kernel.
    main_kernel<<<BQN*NCHUNK, 512, SMEM_BYTES>>>(fq, fs);
    ns_kernel<<<NB*NN, 224>>>(fs);

    int loOff = -1, clsOff = -1;
    if(out_size >= NBQ + BQN){ loOff = 0; clsOff = NBQ; }      // 900: both, logits first
    else if(out_size == NBQ){ loOff = 0; }                     // 150: logits only
    else if(out_size == BQN){ clsOff = 0; }                    // 750: cls only
    else { loOff = 0; }                                        // fallback
    finalize_kernel<<<NBQ, 256>>>(xq, xs, (float*)d_out, loOff, clsOff);
}